// round 8
// baseline (speedup 1.0000x reference)
#include <cuda_runtime.h>
#include <math.h>
#include <stdint.h>

#define Bsz 2
#define Sq  2048
#define Dm  1024
#define Hn  8
#define NEGV (-1e10f)

// Scratch (device globals; no allocations allowed)
__device__ float g_xr[Bsz * Sq * Dm];       // tf32-rounded x
__device__ float g_q[Bsz * Sq * Dm];        // q (tf32-rounded)
__device__ float g_qT[Bsz * Sq * Dm];       // q transposed per batch [D][S]
__device__ float g_scores[Bsz * Sq * Sq];   // scores / probs
__device__ float g_head[Bsz * Sq * Dm];     // head ; later ffn act
__device__ float g_h[Bsz * Sq * Dm];        // h
__device__ float g_weffT[Dm * Dm];          // folded+transposed out_kernel
__device__ float g_wiT[Dm * Dm];            // wi transposed

// ---------------- helpers ----------------
__device__ __forceinline__ float tf32r(float x) {
    uint32_t u;
    asm("cvt.rna.tf32.f32 %0, %1;" : "=r"(u) : "f"(x));
    return __uint_as_float(u);
}
__device__ __forceinline__ uint32_t smem_u32(const void* p) {
    uint32_t a;
    asm("{ .reg .u64 t; cvta.to.shared.u64 t, %1; cvt.u32.u64 %0, t; }" : "=r"(a) : "l"(p));
    return a;
}
#define CPA(d, s)  asm volatile("cp.async.cg.shared.global [%0], [%1], 16;" :: "r"(d), "l"(s) : "memory")
#define CPC()      asm volatile("cp.async.commit_group;" ::: "memory")
#define CPW(n)     asm volatile("cp.async.wait_group %0;" :: "n"(n) : "memory")
#define LDSM4(r0, r1, r2, r3, a) \
    asm volatile("ldmatrix.sync.aligned.m8n8.x4.shared.b16 {%0,%1,%2,%3}, [%4];" \
        : "=r"(r0), "=r"(r1), "=r"(r2), "=r"(r3) : "r"(a))

// ---------------------------------------------------------------------------
// tf32 mma.sync GEMM, 4-stage cp.async pipeline, ldmatrix fragment feed.
// CTA tile 128x256, 512 threads (16 warps, 2x8 grid of 64x32 warp tiles).
// Sized so every GEMM in this problem runs in ONE wave on 148 SMs.
// C[M,N] = epi(A[M,K] @ B^T), B stored [N][K] row-major (all operands NT).
// Smem stage: rows x 64B (16 tf32); physChunk = chunk ^ ((row>>1)&3).
// EPI: 0 plain | 1 scale+causal | 2 +residual | 3 +bias | 4 swish
// CK: truncate K at (blockRow+1)*128.  RND: tf32-round stored output.
// ---------------------------------------------------------------------------
#define TM   128
#define TN   256
#define BKk  16
#define ASZA 8192     // 128 rows * 64B
#define ASZB 16384    // 256 rows * 64B
#define NSTG 4
#define DSMEM (NSTG * (ASZA + ASZB))   // 96 KB

template <int EPI, bool CK, bool RND>
__global__ __launch_bounds__(512, 1)
void tgemm(const float* __restrict__ A, const float* __restrict__ B,
           float* __restrict__ C, int M, int N, int K,
           long sA, long sB, long sC, float alpha,
           const float* __restrict__ bias, const float* __restrict__ resid, long sR)
{
    const int m0 = blockIdx.y * TM;
    const int n0 = blockIdx.x * TN;
    if (EPI == 1 && n0 > m0 + TM - 1) return;   // tile fully above diagonal
    const int bz = blockIdx.z;
    A += (size_t)bz * sA;  B += (size_t)bz * sB;  C += (size_t)bz * sC;
    const int Keff = CK ? min(K, (int)(blockIdx.y + 1) * TM) : K;
    const int NK = Keff / BKk;

    extern __shared__ char smb[];
    const uint32_t smA = smem_u32(smb);
    const uint32_t smB = smA + NSTG * ASZA;

    const int t    = threadIdx.x;
    const int lane = t & 31;
    const int wid  = t >> 5;          // 0..15
    const int wRow = wid >> 3;        // 0..1
    const int wCol = wid & 7;         // 0..7

    const int lrow  = t >> 2;         // 0..127
    const int lchnk = t & 3;

    auto load_stage = [&](int s, int kc) {
        const uint32_t da = smA + s * ASZA;
        const uint32_t db = smB + s * ASZB;
        {
            const int row  = lrow;
            const int phys = lchnk ^ ((row >> 1) & 3);
            CPA(da + row * 64 + phys * 16,
                A + (size_t)(m0 + row) * K + kc * BKk + lchnk * 4);
        }
#pragma unroll
        for (int r = 0; r < 2; r++) {
            const int row  = lrow + r * 128;
            const int phys = lchnk ^ ((row >> 1) & 3);
            CPA(db + row * 64 + phys * 16,
                B + (size_t)(n0 + row) * K + kc * BKk + lchnk * 4);
        }
    };

    // ldmatrix per-lane source rows / chunk-halves (loop-invariant)
    const int aRowOff = (lane & 7) + ((lane >> 3) & 1) * 8;
    const int aChHalf = lane >> 4;
    const int bRowOff = ((lane >> 4) & 1) * 8 + (lane & 7);
    const int bChHalf = (lane >> 3) & 1;

    float acc[4][4][4];
#pragma unroll
    for (int i = 0; i < 4; i++)
#pragma unroll
        for (int j = 0; j < 4; j++)
#pragma unroll
            for (int e = 0; e < 4; e++) acc[i][j][e] = 0.f;

#pragma unroll
    for (int s = 0; s < NSTG - 1; s++) { load_stage(s, s); CPC(); }

    for (int it = 0; it < NK; it++) {
        CPW(2);
        __syncthreads();
        if (it + NSTG - 1 < NK) load_stage((it + NSTG - 1) & (NSTG - 1), it + NSTG - 1);
        CPC();

        const int s = it & (NSTG - 1);
        const uint32_t aBase = smA + s * ASZA;
        const uint32_t bBase = smB + s * ASZB;

#pragma unroll
        for (int kk = 0; kk < 2; kk++) {
            const int kb4 = kk * 2;
            uint32_t af[4][4], bf[4][2];
#pragma unroll
            for (int mt = 0; mt < 4; mt++) {
                const int row   = wRow * 64 + mt * 16 + aRowOff;
                const int chunk = kb4 + aChHalf;
                const uint32_t addr = aBase + row * 64 + ((chunk ^ ((row >> 1) & 3)) << 4);
                LDSM4(af[mt][0], af[mt][1], af[mt][2], af[mt][3], addr);
            }
#pragma unroll
            for (int p = 0; p < 2; p++) {
                const int row   = wCol * 32 + p * 16 + bRowOff;
                const int chunk = kb4 + bChHalf;
                const uint32_t addr = bBase + row * 64 + ((chunk ^ ((row >> 1) & 3)) << 4);
                LDSM4(bf[2 * p][0], bf[2 * p][1], bf[2 * p + 1][0], bf[2 * p + 1][1], addr);
            }
#pragma unroll
            for (int mt = 0; mt < 4; mt++)
#pragma unroll
                for (int nt = 0; nt < 4; nt++) {
                    float* d = acc[mt][nt];
                    asm volatile(
                        "mma.sync.aligned.m16n8k8.row.col.f32.tf32.tf32.f32 "
                        "{%0,%1,%2,%3}, {%4,%5,%6,%7}, {%8,%9}, {%0,%1,%2,%3};"
                        : "+f"(d[0]), "+f"(d[1]), "+f"(d[2]), "+f"(d[3])
                        : "r"(af[mt][0]), "r"(af[mt][1]), "r"(af[mt][2]), "r"(af[mt][3]),
                          "r"(bf[nt][0]), "r"(bf[nt][1]));
                }
        }
    }

    // ---- epilogue ----
    const int g = lane >> 2;
    const int c = lane & 3;
#pragma unroll
    for (int mt = 0; mt < 4; mt++) {
#pragma unroll
        for (int nt = 0; nt < 4; nt++) {
            const int row0 = m0 + wRow * 64 + mt * 16 + g;
            const int col0 = n0 + wCol * 32 + nt * 8 + 2 * c;
            float* d = acc[mt][nt];
#pragma unroll
            for (int half = 0; half < 2; half++) {
                const int row = row0 + half * 8;
                float v0 = d[half * 2 + 0];
                float v1 = d[half * 2 + 1];
                if (EPI == 1) {
                    v0 = (col0 <= row)     ? v0 * alpha : NEGV;
                    v1 = (col0 + 1 <= row) ? v1 * alpha : NEGV;
                }
                if (EPI == 2) {
                    const float* rr = resid + (size_t)bz * sR + (size_t)row * N + col0;
                    v0 += rr[0]; v1 += rr[1];
                }
                if (EPI == 3) { v0 += bias[col0]; v1 += bias[col0 + 1]; }
                if (EPI == 4) {
                    v0 = v0 / (1.f + __expf(-v0));
                    v1 = v1 / (1.f + __expf(-v1));
                }
                if (RND) { v0 = tf32r(v0); v1 = tf32r(v1); }
                *(float2*)&C[(size_t)row * N + col0] = make_float2(v0, v1);
            }
        }
    }
}

// ---------------------------------------------------------------------------
__global__ void round_copy(const float* __restrict__ in, float* __restrict__ out) {
    const int i = (blockIdx.x * 256 + threadIdx.x) * 4;
    float4 v = *(const float4*)(in + i);
    v.x = tf32r(v.x); v.y = tf32r(v.y); v.z = tf32r(v.z); v.w = tf32r(v.w);
    *(float4*)(out + i) = v;
}

__global__ void transpose_b(const float* __restrict__ in, float* __restrict__ out,
                            int R, int C, long sI, long sO) {
    __shared__ float tile[32][33];
    const float* I = in  + (size_t)blockIdx.z * sI;
    float*       O = out + (size_t)blockIdx.z * sO;
    const int r0 = blockIdx.y * 32, c0 = blockIdx.x * 32;
    const int tx = threadIdx.x, ty = threadIdx.y;
#pragma unroll
    for (int j = 0; j < 4; j++)
        tile[ty + j * 8][tx] = tf32r(I[(size_t)(r0 + ty + j * 8) * C + c0 + tx]);
    __syncthreads();
#pragma unroll
    for (int j = 0; j < 4; j++)
        O[(size_t)(c0 + ty + j * 8) * R + r0 + tx] = tile[tx][ty + j * 8];
}

__global__ void fold_transpose(const float* __restrict__ ok, float* __restrict__ out) {
    __shared__ float tile[32][33];
    const int k0 = blockIdx.x * 32, n0 = blockIdx.y * 32;
    const int tx = threadIdx.x, ty = threadIdx.y;
    float acc[4] = {0.f, 0.f, 0.f, 0.f};
    for (int h = 0; h < Hn; h++)
#pragma unroll
        for (int j = 0; j < 4; j++)
            acc[j] += ok[(size_t)h * Dm * Dm + (size_t)(k0 + ty + 8 * j) * Dm + n0 + tx];
#pragma unroll
    for (int j = 0; j < 4; j++) tile[ty + 8 * j][tx] = tf32r(acc[j]);
    __syncthreads();
#pragma unroll
    for (int j = 0; j < 4; j++)
        out[(size_t)(n0 + ty + 8 * j) * Dm + k0 + tx] = tile[tx][ty + 8 * j];
}

// ---------------------------------------------------------------------------
__global__ void softmax_rows(float* __restrict__ sc) {
    const int rowg = blockIdx.x;
    const int b = rowg / Sq, r = rowg % Sq;
    float* p = sc + (size_t)b * Sq * Sq + (size_t)r * Sq;
    const int L = ((r >> 7) + 1) << 7;
    const int t = threadIdx.x;

    float vals[8];
    int cnt = 0;
    float mx = -INFINITY;
    for (int j = t; j < L; j += 256) { float v = p[j]; vals[cnt++] = v; mx = fmaxf(mx, v); }

    __shared__ float red[256];
    red[t] = mx; __syncthreads();
    for (int s = 128; s > 0; s >>= 1) { if (t < s) red[t] = fmaxf(red[t], red[t + s]); __syncthreads(); }
    mx = red[0]; __syncthreads();

    float sum = 0.f;
    for (int i = 0; i < cnt; i++) { vals[i] = __expf(vals[i] - mx); sum += vals[i]; }
    red[t] = sum; __syncthreads();
    for (int s = 128; s > 0; s >>= 1) { if (t < s) red[t] += red[t + s]; __syncthreads(); }
    const float inv = 1.f / red[0];

    cnt = 0;
    for (int j = t; j < L; j += 256) p[j] = tf32r(vals[cnt++] * inv);
}

__global__ void layernorm_rows(float* __restrict__ h) {
    const int row = blockIdx.x;
    float* p = h + (size_t)row * Dm;
    const int t = threadIdx.x;
    float4 v = *(float4*)&p[t * 4];
    float s  = v.x + v.y + v.z + v.w;
    float sq = v.x * v.x + v.y * v.y + v.z * v.z + v.w * v.w;

    __shared__ float rs[256], rq[256];
    rs[t] = s; rq[t] = sq; __syncthreads();
    for (int k = 128; k > 0; k >>= 1) {
        if (t < k) { rs[t] += rs[t + k]; rq[t] += rq[t + k]; }
        __syncthreads();
    }
    const float mean = rs[0] * (1.f / Dm);
    const float var  = rq[0] * (1.f / Dm) - mean * mean;
    const float inv  = rsqrtf(var + 1e-5f);
    v.x = tf32r((v.x - mean) * inv);
    v.y = tf32r((v.y - mean) * inv);
    v.z = tf32r((v.z - mean) * inv);
    v.w = tf32r((v.w - mean) * inv);
    *(float4*)&p[t * 4] = v;
}

// ---------------------------------------------------------------------------
extern "C" void kernel_launch(void* const* d_in, const int* in_sizes, int n_in,
                              void* d_out, int out_size)
{
    const float* x  = (const float*)d_in[0];
    const float* wi = (const float*)d_in[2];
    const float* ok = (const float*)d_in[3];
    const float* ob = (const float*)d_in[4];
    float* out = (float*)d_out;

    float *xr, *q, *qT, *sc, *head, *h, *weffT, *wiT;
    cudaGetSymbolAddress((void**)&xr,    g_xr);
    cudaGetSymbolAddress((void**)&q,     g_q);
    cudaGetSymbolAddress((void**)&qT,    g_qT);
    cudaGetSymbolAddress((void**)&sc,    g_scores);
    cudaGetSymbolAddress((void**)&head,  g_head);
    cudaGetSymbolAddress((void**)&h,     g_h);
    cudaGetSymbolAddress((void**)&weffT, g_weffT);
    cudaGetSymbolAddress((void**)&wiT,   g_wiT);

    cudaFuncSetAttribute(tgemm<0, false, true>,  cudaFuncAttributeMaxDynamicSharedMemorySize, DSMEM);
    cudaFuncSetAttribute(tgemm<1, false, false>, cudaFuncAttributeMaxDynamicSharedMemorySize, DSMEM);
    cudaFuncSetAttribute(tgemm<2, true,  true>,  cudaFuncAttributeMaxDynamicSharedMemorySize, DSMEM);
    cudaFuncSetAttribute(tgemm<3, false, false>, cudaFuncAttributeMaxDynamicSharedMemorySize, DSMEM);
    cudaFuncSetAttribute(tgemm<4, false, true>,  cudaFuncAttributeMaxDynamicSharedMemorySize, DSMEM);
    cudaFuncSetAttribute(tgemm<0, false, false>, cudaFuncAttributeMaxDynamicSharedMemorySize, DSMEM);

    const int MS = Bsz * Sq;            // 4096
    const long sQ  = (long)Sq * Dm;
    const long sSS = (long)Sq * Sq;

    round_copy<<<(Bsz * Sq * Dm) / 1024, 256>>>(x, xr);
    fold_transpose<<<dim3(Dm / 32, Dm / 32), dim3(32, 8)>>>(ok, weffT);
    transpose_b<<<dim3(Dm / 32, Dm / 32, 1), dim3(32, 8)>>>(wi, wiT, Dm, Dm, 0, 0);

    // q = x @ wi (rounded output) — 128 CTAs, 1 wave
    tgemm<0, false, true><<<dim3(Dm / TN, MS / TM, 1), 512, DSMEM>>>(
        xr, wiT, q, MS, Dm, Dm, 0, 0, 0, 0.f, nullptr, nullptr, 0);

    transpose_b<<<dim3(Dm / 32, Sq / 32, Bsz), dim3(32, 8)>>>(q, qT, Sq, Dm, sQ, sQ);

    // scores = (q @ q^T)/32 causal — ~144 working CTAs, 1 wave
    tgemm<1, false, false><<<dim3(Sq / TN, Sq / TM, Bsz), 512, DSMEM>>>(
        q, q, sc, Sq, Sq, Dm, sQ, sQ, sSS, 1.f / 32.f, nullptr, nullptr, 0);

    softmax_rows<<<Bsz * Sq, 256>>>(sc);

    // head = P @ q + q — 128 CTAs, 1 wave
    tgemm<2, true, true><<<dim3(Dm / TN, Sq / TM, Bsz), 512, DSMEM>>>(
        sc, qT, head, Sq, Dm, Sq, sSS, sQ, sQ, 0.f, nullptr, q, sQ);

    // h = head @ Weff + bias — 128 CTAs
    tgemm<3, false, false><<<dim3(Dm / TN, MS / TM, 1), 512, DSMEM>>>(
        head, weffT, h, MS, Dm, Dm, 0, 0, 0, 0.f, ob, nullptr, 0);

    layernorm_rows<<<Bsz * Sq, 256>>>(h);

    // act = swish(h @ wi) — 128 CTAs
    tgemm<4, false, true><<<dim3(Dm / TN, MS / TM, 1), 512, DSMEM>>>(
        h, wiT, head, MS, Dm, Dm, 0, 0, 0, 0.f, nullptr, nullptr, 0);

    // out = act @ wi — 128 CTAs
    tgemm<0, false, false><<<dim3(Dm / TN, MS / TM, 1), 512, DSMEM>>>(
        head, wiT, out, MS, Dm, Dm, 0, 0, 0, 0.f, nullptr, nullptr, 0);
}

// round 9
// speedup vs baseline: 1.1435x; 1.1435x over previous
#include <cuda_runtime.h>
#include <math.h>
#include <stdint.h>

#define Bsz 2
#define Sq  2048
#define Dm  1024
#define Hn  8
#define NEGV (-1e10f)

// Scratch (device globals; no allocations allowed)
__device__ float g_xr[Bsz * Sq * Dm];       // tf32-rounded x
__device__ float g_q[Bsz * Sq * Dm];        // q (tf32-rounded)
__device__ float g_qT[Bsz * Sq * Dm];       // q transposed per batch [D][S]
__device__ float g_scores[Bsz * Sq * Sq];   // scores / probs
__device__ float g_head[Bsz * Sq * Dm];     // head ; later ffn act
__device__ float g_h[Bsz * Sq * Dm];        // h
__device__ float g_weffT[Dm * Dm];          // folded+transposed out_kernel
__device__ float g_wiT[Dm * Dm];            // wi transposed

// ---------------- helpers ----------------
__device__ __forceinline__ float tf32r(float x) {
    uint32_t u;
    asm("cvt.rna.tf32.f32 %0, %1;" : "=r"(u) : "f"(x));
    return __uint_as_float(u);
}
__device__ __forceinline__ uint32_t smem_u32(const void* p) {
    uint32_t a;
    asm("{ .reg .u64 t; cvta.to.shared.u64 t, %1; cvt.u32.u64 %0, t; }" : "=r"(a) : "l"(p));
    return a;
}
#define CPA(d, s)  asm volatile("cp.async.cg.shared.global [%0], [%1], 16;" :: "r"(d), "l"(s) : "memory")
#define CPC()      asm volatile("cp.async.commit_group;" ::: "memory")
#define CPW(n)     asm volatile("cp.async.wait_group %0;" :: "n"(n) : "memory")
#define LDSM4(r0, r1, r2, r3, a) \
    asm volatile("ldmatrix.sync.aligned.m8n8.x4.shared.b16 {%0,%1,%2,%3}, [%4];" \
        : "=r"(r0), "=r"(r1), "=r"(r2), "=r"(r3) : "r"(a))

// ---------------------------------------------------------------------------
// tf32 mma.sync GEMM, 3-stage cp.async pipeline, BK=32 per stage.
// CTA 128x128, 256 threads (8 warps, 2x4 of 64x32 warp tiles), 2 CTAs/SM.
// C[M,N] = epi(A[M,K] @ B^T), B stored [N][K] row-major (all operands NT).
// Smem stage: 128 rows x 128B (32 tf32, 8 chunks of 16B);
// physChunk = chunk ^ (row & 7)  (bijective per chunk over 8 rows ->
// conflict-free for both cp.async 16B stores and ldmatrix fetches).
// EPI: 0 plain | 1 scale+causal | 2 +residual | 3 +bias | 4 swish
// CK: truncate K at (blockRow+1)*128.  RND: tf32-round stored output.
// ---------------------------------------------------------------------------
#define TILE 128
#define BKk  32
#define ASZ  16384
#define NSTG 3
#define DSMEM (2 * NSTG * ASZ)   // 96 KB

template <int EPI, bool CK, bool RND>
__global__ __launch_bounds__(256, 2)
void tgemm(const float* __restrict__ A, const float* __restrict__ B,
           float* __restrict__ C, int M, int N, int K,
           long sA, long sB, long sC, float alpha,
           const float* __restrict__ bias, const float* __restrict__ resid, long sR)
{
    if (EPI == 1 && blockIdx.x > blockIdx.y) return;
    const int bz = blockIdx.z;
    A += (size_t)bz * sA;  B += (size_t)bz * sB;  C += (size_t)bz * sC;
    const int m0 = blockIdx.y * TILE;
    const int n0 = blockIdx.x * TILE;
    const int Keff = CK ? min(K, (int)(blockIdx.y + 1) * TILE) : K;
    const int NK = Keff / BKk;

    extern __shared__ char smb[];
    const uint32_t smA = smem_u32(smb);
    const uint32_t smB = smA + NSTG * ASZ;

    const int t    = threadIdx.x;
    const int lane = t & 31;
    const int wid  = t >> 5;
    const int wRow = wid >> 2;        // 0..1
    const int wCol = wid & 3;         // 0..3

    const int lrow  = t >> 3;         // 0..31
    const int lchnk = t & 7;          // 0..7

    auto load_stage = [&](int s, int kc) {
        const uint32_t da = smA + s * ASZ;
        const uint32_t db = smB + s * ASZ;
#pragma unroll
        for (int r = 0; r < 4; r++) {
            const int row  = lrow + r * 32;
            const int phys = lchnk ^ (row & 7);
            CPA(da + row * 128 + phys * 16,
                A + (size_t)(m0 + row) * K + kc * BKk + lchnk * 4);
            CPA(db + row * 128 + phys * 16,
                B + (size_t)(n0 + row) * K + kc * BKk + lchnk * 4);
        }
    };

    // ldmatrix per-lane source rows / chunk-halves (loop-invariant)
    const int aRowOff = (lane & 7) + ((lane >> 3) & 1) * 8;
    const int aChHalf = lane >> 4;
    const int bRowOff = ((lane >> 4) & 1) * 8 + (lane & 7);
    const int bChHalf = (lane >> 3) & 1;

    float acc[4][4][4];
#pragma unroll
    for (int i = 0; i < 4; i++)
#pragma unroll
        for (int j = 0; j < 4; j++)
#pragma unroll
            for (int e = 0; e < 4; e++) acc[i][j][e] = 0.f;

#pragma unroll
    for (int s = 0; s < NSTG - 1; s++) { load_stage(s, s); CPC(); }

    for (int it = 0; it < NK; it++) {
        CPW(1);
        __syncthreads();
        if (it + NSTG - 1 < NK) load_stage((it + NSTG - 1) % NSTG, it + NSTG - 1);
        CPC();

        const int s = it % NSTG;
        const uint32_t aBase = smA + s * ASZ;
        const uint32_t bBase = smB + s * ASZ;

#pragma unroll
        for (int kk = 0; kk < 4; kk++) {
            const int kb4 = kk * 2;          // 16B-chunk base within row (0..7)
            uint32_t af[4][4], bf[4][2];
#pragma unroll
            for (int mt = 0; mt < 4; mt++) {
                const int row   = wRow * 64 + mt * 16 + aRowOff;
                const int chunk = kb4 + aChHalf;
                const uint32_t addr = aBase + row * 128 + ((chunk ^ (row & 7)) << 4);
                LDSM4(af[mt][0], af[mt][1], af[mt][2], af[mt][3], addr);
            }
#pragma unroll
            for (int p = 0; p < 2; p++) {
                const int row   = wCol * 32 + p * 16 + bRowOff;
                const int chunk = kb4 + bChHalf;
                const uint32_t addr = bBase + row * 128 + ((chunk ^ (row & 7)) << 4);
                LDSM4(bf[2 * p][0], bf[2 * p][1], bf[2 * p + 1][0], bf[2 * p + 1][1], addr);
            }
#pragma unroll
            for (int mt = 0; mt < 4; mt++)
#pragma unroll
                for (int nt = 0; nt < 4; nt++) {
                    float* d = acc[mt][nt];
                    asm volatile(
                        "mma.sync.aligned.m16n8k8.row.col.f32.tf32.tf32.f32 "
                        "{%0,%1,%2,%3}, {%4,%5,%6,%7}, {%8,%9}, {%0,%1,%2,%3};"
                        : "+f"(d[0]), "+f"(d[1]), "+f"(d[2]), "+f"(d[3])
                        : "r"(af[mt][0]), "r"(af[mt][1]), "r"(af[mt][2]), "r"(af[mt][3]),
                          "r"(bf[nt][0]), "r"(bf[nt][1]));
                }
        }
    }

    // ---- epilogue ----
    const int g = lane >> 2;
    const int c = lane & 3;
#pragma unroll
    for (int mt = 0; mt < 4; mt++) {
#pragma unroll
        for (int nt = 0; nt < 4; nt++) {
            const int row0 = m0 + wRow * 64 + mt * 16 + g;
            const int col0 = n0 + wCol * 32 + nt * 8 + 2 * c;
            float* d = acc[mt][nt];
#pragma unroll
            for (int half = 0; half < 2; half++) {
                const int row = row0 + half * 8;
                float v0 = d[half * 2 + 0];
                float v1 = d[half * 2 + 1];
                if (EPI == 1) {
                    v0 = (col0 <= row)     ? v0 * alpha : NEGV;
                    v1 = (col0 + 1 <= row) ? v1 * alpha : NEGV;
                }
                if (EPI == 2) {
                    const float* rr = resid + (size_t)bz * sR + (size_t)row * N + col0;
                    v0 += rr[0]; v1 += rr[1];
                }
                if (EPI == 3) { v0 += bias[col0]; v1 += bias[col0 + 1]; }
                if (EPI == 4) {
                    v0 = v0 / (1.f + __expf(-v0));
                    v1 = v1 / (1.f + __expf(-v1));
                }
                if (RND) { v0 = tf32r(v0); v1 = tf32r(v1); }
                *(float2*)&C[(size_t)row * N + col0] = make_float2(v0, v1);
            }
        }
    }
}

// ---------------------------------------------------------------------------
__global__ void round_copy(const float* __restrict__ in, float* __restrict__ out) {
    const int i = (blockIdx.x * 256 + threadIdx.x) * 4;
    float4 v = *(const float4*)(in + i);
    v.x = tf32r(v.x); v.y = tf32r(v.y); v.z = tf32r(v.z); v.w = tf32r(v.w);
    *(float4*)(out + i) = v;
}

__global__ void transpose_b(const float* __restrict__ in, float* __restrict__ out,
                            int R, int C, long sI, long sO) {
    __shared__ float tile[32][33];
    const float* I = in  + (size_t)blockIdx.z * sI;
    float*       O = out + (size_t)blockIdx.z * sO;
    const int r0 = blockIdx.y * 32, c0 = blockIdx.x * 32;
    const int tx = threadIdx.x, ty = threadIdx.y;
#pragma unroll
    for (int j = 0; j < 4; j++)
        tile[ty + j * 8][tx] = tf32r(I[(size_t)(r0 + ty + j * 8) * C + c0 + tx]);
    __syncthreads();
#pragma unroll
    for (int j = 0; j < 4; j++)
        O[(size_t)(c0 + ty + j * 8) * R + r0 + tx] = tile[tx][ty + j * 8];
}

__global__ void fold_transpose(const float* __restrict__ ok, float* __restrict__ out) {
    __shared__ float tile[32][33];
    const int k0 = blockIdx.x * 32, n0 = blockIdx.y * 32;
    const int tx = threadIdx.x, ty = threadIdx.y;
    float acc[4] = {0.f, 0.f, 0.f, 0.f};
    for (int h = 0; h < Hn; h++)
#pragma unroll
        for (int j = 0; j < 4; j++)
            acc[j] += ok[(size_t)h * Dm * Dm + (size_t)(k0 + ty + 8 * j) * Dm + n0 + tx];
#pragma unroll
    for (int j = 0; j < 4; j++) tile[ty + 8 * j][tx] = tf32r(acc[j]);
    __syncthreads();
#pragma unroll
    for (int j = 0; j < 4; j++)
        out[(size_t)(n0 + ty + 8 * j) * Dm + k0 + tx] = tile[tx][ty + 8 * j];
}

// ---------------------------------------------------------------------------
__global__ void softmax_rows(float* __restrict__ sc) {
    const int rowg = blockIdx.x;
    const int b = rowg / Sq, r = rowg % Sq;
    float* p = sc + (size_t)b * Sq * Sq + (size_t)r * Sq;
    const int L = ((r >> 7) + 1) << 7;
    const int t = threadIdx.x;

    float vals[8];
    int cnt = 0;
    float mx = -INFINITY;
    for (int j = t; j < L; j += 256) { float v = p[j]; vals[cnt++] = v; mx = fmaxf(mx, v); }

    __shared__ float red[256];
    red[t] = mx; __syncthreads();
    for (int s = 128; s > 0; s >>= 1) { if (t < s) red[t] = fmaxf(red[t], red[t + s]); __syncthreads(); }
    mx = red[0]; __syncthreads();

    float sum = 0.f;
    for (int i = 0; i < cnt; i++) { vals[i] = __expf(vals[i] - mx); sum += vals[i]; }
    red[t] = sum; __syncthreads();
    for (int s = 128; s > 0; s >>= 1) { if (t < s) red[t] += red[t + s]; __syncthreads(); }
    const float inv = 1.f / red[0];

    cnt = 0;
    for (int j = t; j < L; j += 256) p[j] = tf32r(vals[cnt++] * inv);
}

__global__ void layernorm_rows(float* __restrict__ h) {
    const int row = blockIdx.x;
    float* p = h + (size_t)row * Dm;
    const int t = threadIdx.x;
    float4 v = *(float4*)&p[t * 4];
    float s  = v.x + v.y + v.z + v.w;
    float sq = v.x * v.x + v.y * v.y + v.z * v.z + v.w * v.w;

    __shared__ float rs[256], rq[256];
    rs[t] = s; rq[t] = sq; __syncthreads();
    for (int k = 128; k > 0; k >>= 1) {
        if (t < k) { rs[t] += rs[t + k]; rq[t] += rq[t + k]; }
        __syncthreads();
    }
    const float mean = rs[0] * (1.f / Dm);
    const float var  = rq[0] * (1.f / Dm) - mean * mean;
    const float inv  = rsqrtf(var + 1e-5f);
    v.x = tf32r((v.x - mean) * inv);
    v.y = tf32r((v.y - mean) * inv);
    v.z = tf32r((v.z - mean) * inv);
    v.w = tf32r((v.w - mean) * inv);
    *(float4*)&p[t * 4] = v;
}

// ---------------------------------------------------------------------------
extern "C" void kernel_launch(void* const* d_in, const int* in_sizes, int n_in,
                              void* d_out, int out_size)
{
    const float* x  = (const float*)d_in[0];
    const float* wi = (const float*)d_in[2];
    const float* ok = (const float*)d_in[3];
    const float* ob = (const float*)d_in[4];
    float* out = (float*)d_out;

    float *xr, *q, *qT, *sc, *head, *h, *weffT, *wiT;
    cudaGetSymbolAddress((void**)&xr,    g_xr);
    cudaGetSymbolAddress((void**)&q,     g_q);
    cudaGetSymbolAddress((void**)&qT,    g_qT);
    cudaGetSymbolAddress((void**)&sc,    g_scores);
    cudaGetSymbolAddress((void**)&head,  g_head);
    cudaGetSymbolAddress((void**)&h,     g_h);
    cudaGetSymbolAddress((void**)&weffT, g_weffT);
    cudaGetSymbolAddress((void**)&wiT,   g_wiT);

    cudaFuncSetAttribute(tgemm<0, false, true>,  cudaFuncAttributeMaxDynamicSharedMemorySize, DSMEM);
    cudaFuncSetAttribute(tgemm<1, false, false>, cudaFuncAttributeMaxDynamicSharedMemorySize, DSMEM);
    cudaFuncSetAttribute(tgemm<2, true,  true>,  cudaFuncAttributeMaxDynamicSharedMemorySize, DSMEM);
    cudaFuncSetAttribute(tgemm<3, false, false>, cudaFuncAttributeMaxDynamicSharedMemorySize, DSMEM);
    cudaFuncSetAttribute(tgemm<4, false, true>,  cudaFuncAttributeMaxDynamicSharedMemorySize, DSMEM);
    cudaFuncSetAttribute(tgemm<0, false, false>, cudaFuncAttributeMaxDynamicSharedMemorySize, DSMEM);

    const int MS = Bsz * Sq;            // 4096
    const long sQ  = (long)Sq * Dm;
    const long sSS = (long)Sq * Sq;

    round_copy<<<(Bsz * Sq * Dm) / 1024, 256>>>(x, xr);
    fold_transpose<<<dim3(Dm / 32, Dm / 32), dim3(32, 8)>>>(ok, weffT);
    transpose_b<<<dim3(Dm / 32, Dm / 32, 1), dim3(32, 8)>>>(wi, wiT, Dm, Dm, 0, 0);

    // q = x @ wi (rounded output)
    tgemm<0, false, true><<<dim3(Dm / TILE, MS / TILE, 1), 256, DSMEM>>>(
        xr, wiT, q, MS, Dm, Dm, 0, 0, 0, 0.f, nullptr, nullptr, 0);

    transpose_b<<<dim3(Dm / 32, Sq / 32, Bsz), dim3(32, 8)>>>(q, qT, Sq, Dm, sQ, sQ);

    // scores = (q @ q^T)/32 causal
    tgemm<1, false, false><<<dim3(Sq / TILE, Sq / TILE, Bsz), 256, DSMEM>>>(
        q, q, sc, Sq, Sq, Dm, sQ, sQ, sSS, 1.f / 32.f, nullptr, nullptr, 0);

    softmax_rows<<<Bsz * Sq, 256>>>(sc);

    // head = P @ q + q
    tgemm<2, true, true><<<dim3(Dm / TILE, Sq / TILE, Bsz), 256, DSMEM>>>(
        sc, qT, head, Sq, Dm, Sq, sSS, sQ, sQ, 0.f, nullptr, q, sQ);

    // h = head @ Weff + bias
    tgemm<3, false, false><<<dim3(Dm / TILE, MS / TILE, 1), 256, DSMEM>>>(
        head, weffT, h, MS, Dm, Dm, 0, 0, 0, 0.f, ob, nullptr, 0);

    layernorm_rows<<<Bsz * Sq, 256>>>(h);

    // act = swish(h @ wi)
    tgemm<4, false, true><<<dim3(Dm / TILE, MS / TILE, 1), 256, DSMEM>>>(
        h, wiT, head, MS, Dm, Dm, 0, 0, 0, 0.f, nullptr, nullptr, 0);

    // out = act @ wi
    tgemm<0, false, false><<<dim3(Dm / TILE, MS / TILE, 1), 256, DSMEM>>>(
        head, wiT, out, MS, Dm, Dm, 0, 0, 0, 0.f, nullptr, nullptr, 0);
}

// round 10
// speedup vs baseline: 1.7641x; 1.5427x over previous
#include <cuda_runtime.h>
#include <cuda_fp16.h>
#include <math.h>
#include <stdint.h>

#define Bsz 2
#define Sq  2048
#define Dm  1024
#define Hn  8
#define NEGV (-1e10f)

// Scratch (device globals; no allocations allowed)
__device__ __half g_xh[Bsz * Sq * Dm];      // fp16 x
__device__ __half g_qh[Bsz * Sq * Dm];      // fp16 q
__device__ __half g_qTh[Bsz * Sq * Dm];     // fp16 q^T per batch
__device__ float  g_sc[Bsz * Sq * Sq];      // fp32 scores
__device__ __half g_ph[Bsz * Sq * Sq];      // fp16 probs
__device__ __half g_headh[Bsz * Sq * Dm];   // fp16 head
__device__ float  g_h[Bsz * Sq * Dm];       // fp32 h (pre-LN)
__device__ __half g_hh[Bsz * Sq * Dm];      // fp16 LN output
__device__ __half g_acth[Bsz * Sq * Dm];    // fp16 ffn activation
__device__ __half g_weffTh[Dm * Dm];        // fp16 folded+transposed out_kernel
__device__ __half g_wiTh[Dm * Dm];          // fp16 wi transposed

// ---------------- helpers ----------------
__device__ __forceinline__ uint32_t smem_u32(const void* p) {
    uint32_t a;
    asm("{ .reg .u64 t; cvta.to.shared.u64 t, %1; cvt.u32.u64 %0, t; }" : "=r"(a) : "l"(p));
    return a;
}
#define CPA(d, s)  asm volatile("cp.async.cg.shared.global [%0], [%1], 16;" :: "r"(d), "l"(s) : "memory")
#define CPC()      asm volatile("cp.async.commit_group;" ::: "memory")
#define CPW(n)     asm volatile("cp.async.wait_group %0;" :: "n"(n) : "memory")
#define LDSM4(r0, r1, r2, r3, a) \
    asm volatile("ldmatrix.sync.aligned.m8n8.x4.shared.b16 {%0,%1,%2,%3}, [%4];" \
        : "=r"(r0), "=r"(r1), "=r"(r2), "=r"(r3) : "r"(a))

// ---------------------------------------------------------------------------
// fp16 mma.sync GEMM (m16n8k16, fp32 accumulate), 3-stage cp.async, BK=32.
// CTA 128x128, 256 threads (8 warps, 2x4 of 64x32 warp tiles), 2 CTAs/SM.
// C[M,N] = epi(A[M,K] @ B^T), A/B fp16, B stored [N][K] row-major (NT).
// Smem stage: 128 rows x 64B (32 halves, 4 chunks of 16B);
// physChunk = chunk ^ ((row>>1)&3)  (conflict-free stores + ldmatrix).
// EPI: 0 plain | 1 scale+causal | 2 +residual(half) | 3 +bias | 4 swish
// CK: truncate K at (blockRow+1)*128.  OUTH: store half2, else float2.
// ---------------------------------------------------------------------------
#define TILE 128
#define BKk  32
#define ASZ  8192
#define NSTG 3
#define DSMEM (2 * NSTG * ASZ)   // 48 KB

template <int EPI, bool CK, bool OUTH>
__global__ __launch_bounds__(256, 2)
void tgemm(const __half* __restrict__ A, const __half* __restrict__ B,
           void* __restrict__ Cv, int M, int N, int K,
           long sA, long sB, long sC, float alpha,
           const float* __restrict__ bias, const __half* __restrict__ resid, long sR)
{
    if (EPI == 1 && blockIdx.x > blockIdx.y) return;
    const int bz = blockIdx.z;
    A += (size_t)bz * sA;  B += (size_t)bz * sB;
    const int m0 = blockIdx.y * TILE;
    const int n0 = blockIdx.x * TILE;
    const int Keff = CK ? min(K, (int)(blockIdx.y + 1) * TILE) : K;
    const int NK = Keff / BKk;

    extern __shared__ char smb[];
    const uint32_t smA = smem_u32(smb);
    const uint32_t smB = smA + NSTG * ASZ;

    const int t    = threadIdx.x;
    const int lane = t & 31;
    const int wid  = t >> 5;
    const int wRow = wid >> 2;        // 0..1
    const int wCol = wid & 3;         // 0..3

    const int lrow  = t >> 2;         // 0..63
    const int lchnk = t & 3;          // 0..3

    auto load_stage = [&](int s, int kc) {
        const uint32_t da = smA + s * ASZ;
        const uint32_t db = smB + s * ASZ;
#pragma unroll
        for (int r = 0; r < 2; r++) {
            const int row  = lrow + r * 64;
            const int phys = lchnk ^ ((row >> 1) & 3);
            CPA(da + row * 64 + phys * 16,
                A + (size_t)(m0 + row) * K + kc * BKk + lchnk * 8);
            CPA(db + row * 64 + phys * 16,
                B + (size_t)(n0 + row) * K + kc * BKk + lchnk * 8);
        }
    };

    // ldmatrix per-lane source rows / chunk-halves (loop-invariant)
    const int aRowOff = lane & 15;                            // rows m0..15 of block
    const int aChHalf = lane >> 4;                            // 0..1
    const int bRowOff = ((lane >> 4) & 1) * 8 + (lane & 7);   // n rows
    const int bChHalf = (lane >> 3) & 1;                      // 0..1

    float acc[4][4][4];
#pragma unroll
    for (int i = 0; i < 4; i++)
#pragma unroll
        for (int j = 0; j < 4; j++)
#pragma unroll
            for (int e = 0; e < 4; e++) acc[i][j][e] = 0.f;

#pragma unroll
    for (int s = 0; s < NSTG - 1; s++) { load_stage(s, s); CPC(); }

    for (int it = 0; it < NK; it++) {
        CPW(1);
        __syncthreads();
        if (it + NSTG - 1 < NK) load_stage((it + NSTG - 1) % NSTG, it + NSTG - 1);
        CPC();

        const int s = it % NSTG;
        const uint32_t aBase = smA + s * ASZ;
        const uint32_t bBase = smB + s * ASZ;

#pragma unroll
        for (int kk = 0; kk < 2; kk++) {      // two k16 halves of BK=32
            const int kb = kk * 2;            // 16B-chunk base (0 or 2)
            uint32_t af[4][4], bf[4][2];
#pragma unroll
            for (int mt = 0; mt < 4; mt++) {
                const int row   = wRow * 64 + mt * 16 + aRowOff;
                const int chunk = kb + aChHalf;
                const uint32_t addr = aBase + row * 64 + ((chunk ^ ((row >> 1) & 3)) << 4);
                LDSM4(af[mt][0], af[mt][1], af[mt][2], af[mt][3], addr);
            }
#pragma unroll
            for (int p = 0; p < 2; p++) {
                const int row   = wCol * 32 + p * 16 + bRowOff;
                const int chunk = kb + bChHalf;
                const uint32_t addr = bBase + row * 64 + ((chunk ^ ((row >> 1) & 3)) << 4);
                LDSM4(bf[2 * p][0], bf[2 * p][1], bf[2 * p + 1][0], bf[2 * p + 1][1], addr);
            }
#pragma unroll
            for (int mt = 0; mt < 4; mt++)
#pragma unroll
                for (int nt = 0; nt < 4; nt++) {
                    float* d = acc[mt][nt];
                    asm volatile(
                        "mma.sync.aligned.m16n8k16.row.col.f32.f16.f16.f32 "
                        "{%0,%1,%2,%3}, {%4,%5,%6,%7}, {%8,%9}, {%0,%1,%2,%3};"
                        : "+f"(d[0]), "+f"(d[1]), "+f"(d[2]), "+f"(d[3])
                        : "r"(af[mt][0]), "r"(af[mt][1]), "r"(af[mt][2]), "r"(af[mt][3]),
                          "r"(bf[nt][0]), "r"(bf[nt][1]));
                }
        }
    }

    // ---- epilogue ----
    float*  Cf = (float*)Cv  + (size_t)bz * sC;
    __half* Ch = (__half*)Cv + (size_t)bz * sC;
    const int g = lane >> 2;
    const int c = lane & 3;
#pragma unroll
    for (int mt = 0; mt < 4; mt++) {
#pragma unroll
        for (int nt = 0; nt < 4; nt++) {
            const int row0 = m0 + wRow * 64 + mt * 16 + g;
            const int col0 = n0 + wCol * 32 + nt * 8 + 2 * c;
            float* d = acc[mt][nt];
#pragma unroll
            for (int half_ = 0; half_ < 2; half_++) {
                const int row = row0 + half_ * 8;
                float v0 = d[half_ * 2 + 0];
                float v1 = d[half_ * 2 + 1];
                if (EPI == 1) {
                    v0 = (col0 <= row)     ? v0 * alpha : NEGV;
                    v1 = (col0 + 1 <= row) ? v1 * alpha : NEGV;
                }
                if (EPI == 2) {
                    const __half* rr = resid + (size_t)bz * sR + (size_t)row * N + col0;
                    v0 += __half2float(rr[0]); v1 += __half2float(rr[1]);
                }
                if (EPI == 3) { v0 += bias[col0]; v1 += bias[col0 + 1]; }
                if (EPI == 4) {
                    v0 = v0 / (1.f + __expf(-v0));
                    v1 = v1 / (1.f + __expf(-v1));
                }
                if (OUTH) {
                    __half2 hv = __floats2half2_rn(v0, v1);
                    *(__half2*)&Ch[(size_t)row * N + col0] = hv;
                } else {
                    *(float2*)&Cf[(size_t)row * N + col0] = make_float2(v0, v1);
                }
            }
        }
    }
}

// ---------------------------------------------------------------------------
__global__ void half_copy(const float* __restrict__ in, __half* __restrict__ out) {
    const int i = (blockIdx.x * 256 + threadIdx.x) * 4;
    float4 v = *(const float4*)(in + i);
    __half2 a = __floats2half2_rn(v.x, v.y);
    __half2 b = __floats2half2_rn(v.z, v.w);
    *(__half2*)(out + i)     = a;
    *(__half2*)(out + i + 2) = b;
}

// fp32 in -> half out transpose
__global__ void transpose_f2h(const float* __restrict__ in, __half* __restrict__ out,
                              int R, int C) {
    __shared__ __half tile[32][34];
    const int r0 = blockIdx.y * 32, c0 = blockIdx.x * 32;
    const int tx = threadIdx.x, ty = threadIdx.y;
#pragma unroll
    for (int j = 0; j < 4; j++)
        tile[ty + j * 8][tx] = __float2half(in[(size_t)(r0 + ty + j * 8) * C + c0 + tx]);
    __syncthreads();
#pragma unroll
    for (int j = 0; j < 4; j++)
        out[(size_t)(c0 + ty + j * 8) * R + r0 + tx] = tile[tx][ty + j * 8];
}

// half in -> half out transpose (batched)
__global__ void transpose_h(const __half* __restrict__ in, __half* __restrict__ out,
                            int R, int C, long sI, long sO) {
    __shared__ __half tile[32][34];
    const __half* I = in  + (size_t)blockIdx.z * sI;
    __half*       O = out + (size_t)blockIdx.z * sO;
    const int r0 = blockIdx.y * 32, c0 = blockIdx.x * 32;
    const int tx = threadIdx.x, ty = threadIdx.y;
#pragma unroll
    for (int j = 0; j < 4; j++)
        tile[ty + j * 8][tx] = I[(size_t)(r0 + ty + j * 8) * C + c0 + tx];
    __syncthreads();
#pragma unroll
    for (int j = 0; j < 4; j++)
        O[(size_t)(c0 + ty + j * 8) * R + r0 + tx] = tile[tx][ty + j * 8];
}

// out[n][k] = half(sum_h ok[h*D*D + k*D + n])
__global__ void fold_transpose(const float* __restrict__ ok, __half* __restrict__ out) {
    __shared__ __half tile[32][34];
    const int k0 = blockIdx.x * 32, n0 = blockIdx.y * 32;
    const int tx = threadIdx.x, ty = threadIdx.y;
    float acc[4] = {0.f, 0.f, 0.f, 0.f};
    for (int h = 0; h < Hn; h++)
#pragma unroll
        for (int j = 0; j < 4; j++)
            acc[j] += ok[(size_t)h * Dm * Dm + (size_t)(k0 + ty + 8 * j) * Dm + n0 + tx];
#pragma unroll
    for (int j = 0; j < 4; j++) tile[ty + 8 * j][tx] = __float2half(acc[j]);
    __syncthreads();
#pragma unroll
    for (int j = 0; j < 4; j++)
        out[(size_t)(n0 + ty + 8 * j) * Dm + k0 + tx] = tile[tx][ty + 8 * j];
}

// ---------------------------------------------------------------------------
// Row softmax over causal prefix: fp32 scores in, fp16 probs out.
// ---------------------------------------------------------------------------
__global__ void softmax_rows(const float* __restrict__ sc, __half* __restrict__ ph) {
    const int rowg = blockIdx.x;
    const int b = rowg / Sq, r = rowg % Sq;
    const float* p = sc + (size_t)b * Sq * Sq + (size_t)r * Sq;
    __half* po = ph + (size_t)b * Sq * Sq + (size_t)r * Sq;
    const int L = ((r >> 7) + 1) << 7;
    const int t = threadIdx.x;

    float vals[8];
    int cnt = 0;
    float mx = -INFINITY;
    for (int j = t; j < L; j += 256) { float v = p[j]; vals[cnt++] = v; mx = fmaxf(mx, v); }

    __shared__ float red[256];
    red[t] = mx; __syncthreads();
    for (int s = 128; s > 0; s >>= 1) { if (t < s) red[t] = fmaxf(red[t], red[t + s]); __syncthreads(); }
    mx = red[0]; __syncthreads();

    float sum = 0.f;
    for (int i = 0; i < cnt; i++) { vals[i] = __expf(vals[i] - mx); sum += vals[i]; }
    red[t] = sum; __syncthreads();
    for (int s = 128; s > 0; s >>= 1) { if (t < s) red[t] += red[t + s]; __syncthreads(); }
    const float inv = 1.f / red[0];

    cnt = 0;
    for (int j = t; j < L; j += 256) po[j] = __float2half(vals[cnt++] * inv);
}

// LayerNorm: fp32 in, fp16 out (separate buffer).
__global__ void layernorm_rows(const float* __restrict__ h, __half* __restrict__ hh) {
    const int row = blockIdx.x;
    const float* p = h + (size_t)row * Dm;
    __half* po = hh + (size_t)row * Dm;
    const int t = threadIdx.x;
    float4 v = *(const float4*)&p[t * 4];
    float s  = v.x + v.y + v.z + v.w;
    float sq = v.x * v.x + v.y * v.y + v.z * v.z + v.w * v.w;

    __shared__ float rs[256], rq[256];
    rs[t] = s; rq[t] = sq; __syncthreads();
    for (int k = 128; k > 0; k >>= 1) {
        if (t < k) { rs[t] += rs[t + k]; rq[t] += rq[t + k]; }
        __syncthreads();
    }
    const float mean = rs[0] * (1.f / Dm);
    const float var  = rq[0] * (1.f / Dm) - mean * mean;
    const float inv  = rsqrtf(var + 1e-5f);
    __half2 a = __floats2half2_rn((v.x - mean) * inv, (v.y - mean) * inv);
    __half2 b = __floats2half2_rn((v.z - mean) * inv, (v.w - mean) * inv);
    *(__half2*)&po[t * 4]     = a;
    *(__half2*)&po[t * 4 + 2] = b;
}

// ---------------------------------------------------------------------------
extern "C" void kernel_launch(void* const* d_in, const int* in_sizes, int n_in,
                              void* d_out, int out_size)
{
    const float* x  = (const float*)d_in[0];
    const float* wi = (const float*)d_in[2];
    const float* ok = (const float*)d_in[3];
    const float* ob = (const float*)d_in[4];
    float* out = (float*)d_out;

    __half *xh, *qh, *qTh, *ph, *headh, *hh, *acth, *weffTh, *wiTh;
    float *sc, *h;
    cudaGetSymbolAddress((void**)&xh,     g_xh);
    cudaGetSymbolAddress((void**)&qh,     g_qh);
    cudaGetSymbolAddress((void**)&qTh,    g_qTh);
    cudaGetSymbolAddress((void**)&sc,     g_sc);
    cudaGetSymbolAddress((void**)&ph,     g_ph);
    cudaGetSymbolAddress((void**)&headh,  g_headh);
    cudaGetSymbolAddress((void**)&h,      g_h);
    cudaGetSymbolAddress((void**)&hh,     g_hh);
    cudaGetSymbolAddress((void**)&acth,   g_acth);
    cudaGetSymbolAddress((void**)&weffTh, g_weffTh);
    cudaGetSymbolAddress((void**)&wiTh,   g_wiTh);

    cudaFuncSetAttribute(tgemm<0, false, true>,  cudaFuncAttributeMaxDynamicSharedMemorySize, DSMEM);
    cudaFuncSetAttribute(tgemm<1, false, false>, cudaFuncAttributeMaxDynamicSharedMemorySize, DSMEM);
    cudaFuncSetAttribute(tgemm<2, true,  true>,  cudaFuncAttributeMaxDynamicSharedMemorySize, DSMEM);
    cudaFuncSetAttribute(tgemm<3, false, false>, cudaFuncAttributeMaxDynamicSharedMemorySize, DSMEM);
    cudaFuncSetAttribute(tgemm<4, false, true>,  cudaFuncAttributeMaxDynamicSharedMemorySize, DSMEM);
    cudaFuncSetAttribute(tgemm<0, false, false>, cudaFuncAttributeMaxDynamicSharedMemorySize, DSMEM);

    const int MS = Bsz * Sq;            // 4096
    const long sQ  = (long)Sq * Dm;
    const long sSS = (long)Sq * Sq;

    // producers: fp16 operands
    half_copy<<<(Bsz * Sq * Dm) / 1024, 256>>>(x, xh);
    fold_transpose<<<dim3(Dm / 32, Dm / 32), dim3(32, 8)>>>(ok, weffTh);
    transpose_f2h<<<dim3(Dm / 32, Dm / 32), dim3(32, 8)>>>(wi, wiTh, Dm, Dm);

    // q = x @ wi (half out)
    tgemm<0, false, true><<<dim3(Dm / TILE, MS / TILE, 1), 256, DSMEM>>>(
        xh, wiTh, qh, MS, Dm, Dm, 0, 0, 0, 0.f, nullptr, nullptr, 0);

    transpose_h<<<dim3(Dm / 32, Sq / 32, Bsz), dim3(32, 8)>>>(qh, qTh, Sq, Dm, sQ, sQ);

    // scores = (q @ q^T)/32 causal (fp32 out)
    tgemm<1, false, false><<<dim3(Sq / TILE, Sq / TILE, Bsz), 256, DSMEM>>>(
        qh, qh, sc, Sq, Sq, Dm, sQ, sQ, sSS, 1.f / 32.f, nullptr, nullptr, 0);

    softmax_rows<<<Bsz * Sq, 256>>>(sc, ph);

    // head = P @ q + q (half out; causal K truncation)
    tgemm<2, true, true><<<dim3(Dm / TILE, Sq / TILE, Bsz), 256, DSMEM>>>(
        ph, qTh, headh, Sq, Dm, Sq, sSS, sQ, sQ, 0.f, nullptr, qh, sQ);

    // h = head @ Weff + bias (fp32 out for LN)
    tgemm<3, false, false><<<dim3(Dm / TILE, MS / TILE, 1), 256, DSMEM>>>(
        headh, weffTh, h, MS, Dm, Dm, 0, 0, 0, 0.f, ob, nullptr, 0);

    layernorm_rows<<<Bsz * Sq, 256>>>(h, hh);

    // act = swish(h @ wi) (half out)
    tgemm<4, false, true><<<dim3(Dm / TILE, MS / TILE, 1), 256, DSMEM>>>(
        hh, wiTh, acth, MS, Dm, Dm, 0, 0, 0, 0.f, nullptr, nullptr, 0);

    // out = act @ wi (fp32 final)
    tgemm<0, false, false><<<dim3(Dm / TILE, MS / TILE, 1), 256, DSMEM>>>(
        acth, wiTh, out, MS, Dm, Dm, 0, 0, 0, 0.f, nullptr, nullptr, 0);
}

// round 11
// speedup vs baseline: 1.8990x; 1.0765x over previous
#include <cuda_runtime.h>
#include <cuda_fp16.h>
#include <math.h>
#include <stdint.h>

#define Bsz 2
#define Sq  2048
#define Dm  1024
#define Hn  8
#define NEGV (-1e10f)

// Scratch (device globals; no allocations allowed)
__device__ __half g_xh[Bsz * Sq * Dm];      // fp16 x
__device__ __half g_qh[Bsz * Sq * Dm];      // fp16 q
__device__ __half g_qTh[Bsz * Sq * Dm];     // fp16 q^T per batch
__device__ float  g_sc[Bsz * Sq * Sq];      // fp32 scores
__device__ __half g_ph[Bsz * Sq * Sq];      // fp16 probs
__device__ __half g_headh[Bsz * Sq * Dm];   // fp16 head
__device__ float  g_h[Bsz * Sq * Dm];       // fp32 h (pre-LN)
__device__ __half g_hh[Bsz * Sq * Dm];      // fp16 LN output
__device__ __half g_acth[Bsz * Sq * Dm];    // fp16 ffn activation
__device__ __half g_weffTh[Dm * Dm];        // fp16 folded+transposed out_kernel
__device__ __half g_wiTh[Dm * Dm];          // fp16 wi transposed

// ---------------- helpers ----------------
__device__ __forceinline__ uint32_t smem_u32(const void* p) {
    uint32_t a;
    asm("{ .reg .u64 t; cvta.to.shared.u64 t, %1; cvt.u32.u64 %0, t; }" : "=r"(a) : "l"(p));
    return a;
}
#define CPA(d, s)  asm volatile("cp.async.cg.shared.global [%0], [%1], 16;" :: "r"(d), "l"(s) : "memory")
#define CPC()      asm volatile("cp.async.commit_group;" ::: "memory")
#define CPW(n)     asm volatile("cp.async.wait_group %0;" :: "n"(n) : "memory")
#define LDSM4(r0, r1, r2, r3, a) \
    asm volatile("ldmatrix.sync.aligned.m8n8.x4.shared.b16 {%0,%1,%2,%3}, [%4];" \
        : "=r"(r0), "=r"(r1), "=r"(r2), "=r"(r3) : "r"(a))

// ---------------------------------------------------------------------------
// fp16 mma.sync GEMM (m16n8k16, fp32 accumulate), 3-stage cp.async, BK=64.
// CTA 128x128, 256 threads (8 warps, 2x4 of 64x32 warp tiles), 2 CTAs/SM.
// C[M,N] = epi(A[M,K] @ B^T), A/B fp16, B stored [N][K] row-major (NT).
// Smem stage: 128 rows x 128B (64 halves, 8 chunks of 16B);
// physChunk = chunk ^ (row & 7)  (conflict-free for cp.async stores and
// ldmatrix fetches: 8 consecutive rows at one logical chunk -> 8 distinct
// 16B bank-groups).
// EPI: 0 plain | 1 scale+causal | 2 +residual(half) | 3 +bias | 4 swish
// CK: truncate K at (blockRow+1)*128.  OUTH: store half2, else float2.
// ---------------------------------------------------------------------------
#define TILE 128
#define BKk  64
#define ASZ  16384
#define NSTG 3
#define DSMEM (2 * NSTG * ASZ)   // 96 KB

template <int EPI, bool CK, bool OUTH>
__global__ __launch_bounds__(256, 2)
void tgemm(const __half* __restrict__ A, const __half* __restrict__ B,
           void* __restrict__ Cv, int M, int N, int K,
           long sA, long sB, long sC, float alpha,
           const float* __restrict__ bias, const __half* __restrict__ resid, long sR)
{
    if (EPI == 1 && blockIdx.x > blockIdx.y) return;
    const int bz = blockIdx.z;
    A += (size_t)bz * sA;  B += (size_t)bz * sB;
    const int m0 = blockIdx.y * TILE;
    const int n0 = blockIdx.x * TILE;
    const int Keff = CK ? min(K, (int)(blockIdx.y + 1) * TILE) : K;
    const int NK = Keff / BKk;

    extern __shared__ char smb[];
    const uint32_t smA = smem_u32(smb);
    const uint32_t smB = smA + NSTG * ASZ;

    const int t    = threadIdx.x;
    const int lane = t & 31;
    const int wid  = t >> 5;
    const int wRow = wid >> 2;        // 0..1
    const int wCol = wid & 3;         // 0..3

    const int lrow  = t >> 3;         // 0..31
    const int lchnk = t & 7;          // 0..7

    auto load_stage = [&](int s, int kc) {
        const uint32_t da = smA + s * ASZ;
        const uint32_t db = smB + s * ASZ;
#pragma unroll
        for (int r = 0; r < 4; r++) {
            const int row  = lrow + r * 32;
            const int phys = lchnk ^ (row & 7);
            CPA(da + row * 128 + phys * 16,
                A + (size_t)(m0 + row) * K + kc * BKk + lchnk * 8);
            CPA(db + row * 128 + phys * 16,
                B + (size_t)(n0 + row) * K + kc * BKk + lchnk * 8);
        }
    };

    // ldmatrix per-lane source rows / chunk-halves (loop-invariant)
    const int aRowOff = lane & 15;                            // 16 rows of m-block
    const int aChHalf = lane >> 4;                            // 0..1
    const int bRowOff = ((lane >> 4) & 1) * 8 + (lane & 7);   // n rows
    const int bChHalf = (lane >> 3) & 1;                      // 0..1

    float acc[4][4][4];
#pragma unroll
    for (int i = 0; i < 4; i++)
#pragma unroll
        for (int j = 0; j < 4; j++)
#pragma unroll
            for (int e = 0; e < 4; e++) acc[i][j][e] = 0.f;

#pragma unroll
    for (int s = 0; s < NSTG - 1; s++) { load_stage(s, s); CPC(); }

    for (int it = 0; it < NK; it++) {
        CPW(1);
        __syncthreads();
        if (it + NSTG - 1 < NK) load_stage((it + NSTG - 1) % NSTG, it + NSTG - 1);
        CPC();

        const int s = it % NSTG;
        const uint32_t aBase = smA + s * ASZ;
        const uint32_t bBase = smB + s * ASZ;

#pragma unroll
        for (int kk = 0; kk < 4; kk++) {      // four k16 steps of BK=64
            const int kb = kk * 2;            // 16B-chunk base (0,2,4,6)
            uint32_t af[4][4], bf[4][2];
#pragma unroll
            for (int mt = 0; mt < 4; mt++) {
                const int row   = wRow * 64 + mt * 16 + aRowOff;
                const int chunk = kb + aChHalf;
                const uint32_t addr = aBase + row * 128 + ((chunk ^ (row & 7)) << 4);
                LDSM4(af[mt][0], af[mt][1], af[mt][2], af[mt][3], addr);
            }
#pragma unroll
            for (int p = 0; p < 2; p++) {
                const int row   = wCol * 32 + p * 16 + bRowOff;
                const int chunk = kb + bChHalf;
                const uint32_t addr = bBase + row * 128 + ((chunk ^ (row & 7)) << 4);
                LDSM4(bf[2 * p][0], bf[2 * p][1], bf[2 * p + 1][0], bf[2 * p + 1][1], addr);
            }
#pragma unroll
            for (int mt = 0; mt < 4; mt++)
#pragma unroll
                for (int nt = 0; nt < 4; nt++) {
                    float* d = acc[mt][nt];
                    asm volatile(
                        "mma.sync.aligned.m16n8k16.row.col.f32.f16.f16.f32 "
                        "{%0,%1,%2,%3}, {%4,%5,%6,%7}, {%8,%9}, {%0,%1,%2,%3};"
                        : "+f"(d[0]), "+f"(d[1]), "+f"(d[2]), "+f"(d[3])
                        : "r"(af[mt][0]), "r"(af[mt][1]), "r"(af[mt][2]), "r"(af[mt][3]),
                          "r"(bf[nt][0]), "r"(bf[nt][1]));
                }
        }
    }

    // ---- epilogue ----
    float*  Cf = (float*)Cv  + (size_t)bz * sC;
    __half* Ch = (__half*)Cv + (size_t)bz * sC;
    const int g = lane >> 2;
    const int c = lane & 3;
#pragma unroll
    for (int mt = 0; mt < 4; mt++) {
#pragma unroll
        for (int nt = 0; nt < 4; nt++) {
            const int row0 = m0 + wRow * 64 + mt * 16 + g;
            const int col0 = n0 + wCol * 32 + nt * 8 + 2 * c;
            float* d = acc[mt][nt];
#pragma unroll
            for (int half_ = 0; half_ < 2; half_++) {
                const int row = row0 + half_ * 8;
                float v0 = d[half_ * 2 + 0];
                float v1 = d[half_ * 2 + 1];
                if (EPI == 1) {
                    v0 = (col0 <= row)     ? v0 * alpha : NEGV;
                    v1 = (col0 + 1 <= row) ? v1 * alpha : NEGV;
                }
                if (EPI == 2) {
                    const __half* rr = resid + (size_t)bz * sR + (size_t)row * N + col0;
                    v0 += __half2float(rr[0]); v1 += __half2float(rr[1]);
                }
                if (EPI == 3) { v0 += bias[col0]; v1 += bias[col0 + 1]; }
                if (EPI == 4) {
                    v0 = v0 / (1.f + __expf(-v0));
                    v1 = v1 / (1.f + __expf(-v1));
                }
                if (OUTH) {
                    __half2 hv = __floats2half2_rn(v0, v1);
                    *(__half2*)&Ch[(size_t)row * N + col0] = hv;
                } else {
                    *(float2*)&Cf[(size_t)row * N + col0] = make_float2(v0, v1);
                }
            }
        }
    }
}

// ---------------------------------------------------------------------------
__global__ void half_copy(const float* __restrict__ in, __half* __restrict__ out) {
    const int i = (blockIdx.x * 256 + threadIdx.x) * 4;
    float4 v = *(const float4*)(in + i);
    __half2 a = __floats2half2_rn(v.x, v.y);
    __half2 b = __floats2half2_rn(v.z, v.w);
    *(__half2*)(out + i)     = a;
    *(__half2*)(out + i + 2) = b;
}

// fp32 in -> half out transpose
__global__ void transpose_f2h(const float* __restrict__ in, __half* __restrict__ out,
                              int R, int C) {
    __shared__ __half tile[32][34];
    const int r0 = blockIdx.y * 32, c0 = blockIdx.x * 32;
    const int tx = threadIdx.x, ty = threadIdx.y;
#pragma unroll
    for (int j = 0; j < 4; j++)
        tile[ty + j * 8][tx] = __float2half(in[(size_t)(r0 + ty + j * 8) * C + c0 + tx]);
    __syncthreads();
#pragma unroll
    for (int j = 0; j < 4; j++)
        out[(size_t)(c0 + ty + j * 8) * R + r0 + tx] = tile[tx][ty + j * 8];
}

// half in -> half out transpose (batched)
__global__ void transpose_h(const __half* __restrict__ in, __half* __restrict__ out,
                            int R, int C, long sI, long sO) {
    __shared__ __half tile[32][34];
    const __half* I = in  + (size_t)blockIdx.z * sI;
    __half*       O = out + (size_t)blockIdx.z * sO;
    const int r0 = blockIdx.y * 32, c0 = blockIdx.x * 32;
    const int tx = threadIdx.x, ty = threadIdx.y;
#pragma unroll
    for (int j = 0; j < 4; j++)
        tile[ty + j * 8][tx] = I[(size_t)(r0 + ty + j * 8) * C + c0 + tx];
    __syncthreads();
#pragma unroll
    for (int j = 0; j < 4; j++)
        O[(size_t)(c0 + ty + j * 8) * R + r0 + tx] = tile[tx][ty + j * 8];
}

// out[n][k] = half(sum_h ok[h*D*D + k*D + n])
__global__ void fold_transpose(const float* __restrict__ ok, __half* __restrict__ out) {
    __shared__ __half tile[32][34];
    const int k0 = blockIdx.x * 32, n0 = blockIdx.y * 32;
    const int tx = threadIdx.x, ty = threadIdx.y;
    float acc[4] = {0.f, 0.f, 0.f, 0.f};
    for (int h = 0; h < Hn; h++)
#pragma unroll
        for (int j = 0; j < 4; j++)
            acc[j] += ok[(size_t)h * Dm * Dm + (size_t)(k0 + ty + 8 * j) * Dm + n0 + tx];
#pragma unroll
    for (int j = 0; j < 4; j++) tile[ty + 8 * j][tx] = __float2half(acc[j]);
    __syncthreads();
#pragma unroll
    for (int j = 0; j < 4; j++)
        out[(size_t)(n0 + ty + 8 * j) * Dm + k0 + tx] = tile[tx][ty + 8 * j];
}

// ---------------------------------------------------------------------------
// Row softmax over causal prefix: fp32 scores in, fp16 probs out.
// ---------------------------------------------------------------------------
__global__ void softmax_rows(const float* __restrict__ sc, __half* __restrict__ ph) {
    const int rowg = blockIdx.x;
    const int b = rowg / Sq, r = rowg % Sq;
    const float* p = sc + (size_t)b * Sq * Sq + (size_t)r * Sq;
    __half* po = ph + (size_t)b * Sq * Sq + (size_t)r * Sq;
    const int L = ((r >> 7) + 1) << 7;
    const int t = threadIdx.x;

    float vals[8];
    int cnt = 0;
    float mx = -INFINITY;
    for (int j = t; j < L; j += 256) { float v = p[j]; vals[cnt++] = v; mx = fmaxf(mx, v); }

    __shared__ float red[256];
    red[t] = mx; __syncthreads();
    for (int s = 128; s > 0; s >>= 1) { if (t < s) red[t] = fmaxf(red[t], red[t + s]); __syncthreads(); }
    mx = red[0]; __syncthreads();

    float sum = 0.f;
    for (int i = 0; i < cnt; i++) { vals[i] = __expf(vals[i] - mx); sum += vals[i]; }
    red[t] = sum; __syncthreads();
    for (int s = 128; s > 0; s >>= 1) { if (t < s) red[t] += red[t + s]; __syncthreads(); }
    const float inv = 1.f / red[0];

    cnt = 0;
    for (int j = t; j < L; j += 256) po[j] = __float2half(vals[cnt++] * inv);
}

// LayerNorm: fp32 in, fp16 out (separate buffer).
__global__ void layernorm_rows(const float* __restrict__ h, __half* __restrict__ hh) {
    const int row = blockIdx.x;
    const float* p = h + (size_t)row * Dm;
    __half* po = hh + (size_t)row * Dm;
    const int t = threadIdx.x;
    float4 v = *(const float4*)&p[t * 4];
    float s  = v.x + v.y + v.z + v.w;
    float sq = v.x * v.x + v.y * v.y + v.z * v.z + v.w * v.w;

    __shared__ float rs[256], rq[256];
    rs[t] = s; rq[t] = sq; __syncthreads();
    for (int k = 128; k > 0; k >>= 1) {
        if (t < k) { rs[t] += rs[t + k]; rq[t] += rq[t + k]; }
        __syncthreads();
    }
    const float mean = rs[0] * (1.f / Dm);
    const float var  = rq[0] * (1.f / Dm) - mean * mean;
    const float inv  = rsqrtf(var + 1e-5f);
    __half2 a = __floats2half2_rn((v.x - mean) * inv, (v.y - mean) * inv);
    __half2 b = __floats2half2_rn((v.z - mean) * inv, (v.w - mean) * inv);
    *(__half2*)&po[t * 4]     = a;
    *(__half2*)&po[t * 4 + 2] = b;
}

// ---------------------------------------------------------------------------
extern "C" void kernel_launch(void* const* d_in, const int* in_sizes, int n_in,
                              void* d_out, int out_size)
{
    const float* x  = (const float*)d_in[0];
    const float* wi = (const float*)d_in[2];
    const float* ok = (const float*)d_in[3];
    const float* ob = (const float*)d_in[4];
    float* out = (float*)d_out;

    __half *xh, *qh, *qTh, *ph, *headh, *hh, *acth, *weffTh, *wiTh;
    float *sc, *h;
    cudaGetSymbolAddress((void**)&xh,     g_xh);
    cudaGetSymbolAddress((void**)&qh,     g_qh);
    cudaGetSymbolAddress((void**)&qTh,    g_qTh);
    cudaGetSymbolAddress((void**)&sc,     g_sc);
    cudaGetSymbolAddress((void**)&ph,     g_ph);
    cudaGetSymbolAddress((void**)&headh,  g_headh);
    cudaGetSymbolAddress((void**)&h,      g_h);
    cudaGetSymbolAddress((void**)&hh,     g_hh);
    cudaGetSymbolAddress((void**)&acth,   g_acth);
    cudaGetSymbolAddress((void**)&weffTh, g_weffTh);
    cudaGetSymbolAddress((void**)&wiTh,   g_wiTh);

    cudaFuncSetAttribute(tgemm<0, false, true>,  cudaFuncAttributeMaxDynamicSharedMemorySize, DSMEM);
    cudaFuncSetAttribute(tgemm<1, false, false>, cudaFuncAttributeMaxDynamicSharedMemorySize, DSMEM);
    cudaFuncSetAttribute(tgemm<2, true,  true>,  cudaFuncAttributeMaxDynamicSharedMemorySize, DSMEM);
    cudaFuncSetAttribute(tgemm<3, false, false>, cudaFuncAttributeMaxDynamicSharedMemorySize, DSMEM);
    cudaFuncSetAttribute(tgemm<4, false, true>,  cudaFuncAttributeMaxDynamicSharedMemorySize, DSMEM);
    cudaFuncSetAttribute(tgemm<0, false, false>, cudaFuncAttributeMaxDynamicSharedMemorySize, DSMEM);

    const int MS = Bsz * Sq;            // 4096
    const long sQ  = (long)Sq * Dm;
    const long sSS = (long)Sq * Sq;

    // producers: fp16 operands
    half_copy<<<(Bsz * Sq * Dm) / 1024, 256>>>(x, xh);
    fold_transpose<<<dim3(Dm / 32, Dm / 32), dim3(32, 8)>>>(ok, weffTh);
    transpose_f2h<<<dim3(Dm / 32, Dm / 32), dim3(32, 8)>>>(wi, wiTh, Dm, Dm);

    // q = x @ wi (half out)
    tgemm<0, false, true><<<dim3(Dm / TILE, MS / TILE, 1), 256, DSMEM>>>(
        xh, wiTh, qh, MS, Dm, Dm, 0, 0, 0, 0.f, nullptr, nullptr, 0);

    transpose_h<<<dim3(Dm / 32, Sq / 32, Bsz), dim3(32, 8)>>>(qh, qTh, Sq, Dm, sQ, sQ);

    // scores = (q @ q^T)/32 causal (fp32 out)
    tgemm<1, false, false><<<dim3(Sq / TILE, Sq / TILE, Bsz), 256, DSMEM>>>(
        qh, qh, sc, Sq, Sq, Dm, sQ, sQ, sSS, 1.f / 32.f, nullptr, nullptr, 0);

    softmax_rows<<<Bsz * Sq, 256>>>(sc, ph);

    // head = P @ q + q (half out; causal K truncation)
    tgemm<2, true, true><<<dim3(Dm / TILE, Sq / TILE, Bsz), 256, DSMEM>>>(
        ph, qTh, headh, Sq, Dm, Sq, sSS, sQ, sQ, 0.f, nullptr, qh, sQ);

    // h = head @ Weff + bias (fp32 out for LN)
    tgemm<3, false, false><<<dim3(Dm / TILE, MS / TILE, 1), 256, DSMEM>>>(
        headh, weffTh, h, MS, Dm, Dm, 0, 0, 0, 0.f, ob, nullptr, 0);

    layernorm_rows<<<Bsz * Sq, 256>>>(h, hh);

    // act = swish(h @ wi) (half out)
    tgemm<4, false, true><<<dim3(Dm / TILE, MS / TILE, 1), 256, DSMEM>>>(
        hh, wiTh, acth, MS, Dm, Dm, 0, 0, 0, 0.f, nullptr, nullptr, 0);

    // out = act @ wi (fp32 final)
    tgemm<0, false, false><<<dim3(Dm / TILE, MS / TILE, 1), 256, DSMEM>>>(
        acth, wiTh, out, MS, Dm, Dm, 0, 0, 0, 0.f, nullptr, nullptr, 0);
}

// round 12
// speedup vs baseline: 2.0103x; 1.0586x over previous
#include <cuda_runtime.h>
#include <cuda_fp16.h>
#include <math.h>
#include <stdint.h>

#define Bsz 2
#define Sq  2048
#define Dm  1024
#define Hn  8
#define NEGV (-1e10f)

// Scratch (device globals; no allocations allowed)
__device__ __half g_xh[Bsz * Sq * Dm];      // fp16 x
__device__ __half g_qh[Bsz * Sq * Dm];      // fp16 q
__device__ __half g_qTh[Bsz * Sq * Dm];     // fp16 q^T per batch
__device__ float  g_sc[Bsz * Sq * Sq];      // fp32 scores
__device__ __half g_ph[Bsz * Sq * Sq];      // fp16 probs
__device__ float  g_hpv[Bsz * Sq * Dm];     // fp32 PV partial accumulator
__device__ __half g_headh[Bsz * Sq * Dm];   // fp16 head
__device__ float  g_h[Bsz * Sq * Dm];       // fp32 h (pre-LN)
__device__ __half g_hh[Bsz * Sq * Dm];      // fp16 LN output
__device__ __half g_acth[Bsz * Sq * Dm];    // fp16 ffn activation
__device__ __half g_weffTh[Dm * Dm];        // fp16 folded+transposed out_kernel
__device__ __half g_wiTh[Dm * Dm];          // fp16 wi transposed

// ---------------- helpers ----------------
__device__ __forceinline__ uint32_t smem_u32(const void* p) {
    uint32_t a;
    asm("{ .reg .u64 t; cvta.to.shared.u64 t, %1; cvt.u32.u64 %0, t; }" : "=r"(a) : "l"(p));
    return a;
}
#define CPA(d, s)  asm volatile("cp.async.cg.shared.global [%0], [%1], 16;" :: "r"(d), "l"(s) : "memory")
#define CPC()      asm volatile("cp.async.commit_group;" ::: "memory")
#define CPW(n)     asm volatile("cp.async.wait_group %0;" :: "n"(n) : "memory")
#define LDSM4(r0, r1, r2, r3, a) \
    asm volatile("ldmatrix.sync.aligned.m8n8.x4.shared.b16 {%0,%1,%2,%3}, [%4];" \
        : "=r"(r0), "=r"(r1), "=r"(r2), "=r"(r3) : "r"(a))

// ---------------------------------------------------------------------------
// fp16 mma.sync GEMM (m16n8k16, fp32 accumulate), 3-stage cp.async, BK=64.
// CTA 128x128, 256 threads (8 warps, 2x4 of 64x32 warp tiles), 2 CTAs/SM.
// C[M,N] = epi(A[M,K] @ B^T), A/B fp16, B stored [N][K] row-major (NT).
// Smem stage: 128 rows x 128B; physChunk = chunk ^ (row & 7) (conflict-free).
// EPI: 0 plain | 1 scale+causal | 3 +bias | 4 swish
//      5 split-K PV: rowTile = gridDim.y-1-by (longest first), z = batch*2+half,
//        each half covers (rowTile+1) BK-iters; epilogue fp32 atomicAdd.
// CK: truncate K at (blockRow+1)*128.  OUTH: store half2, else float2.
// ---------------------------------------------------------------------------
#define TILE 128
#define BKk  64
#define ASZ  16384
#define NSTG 3
#define DSMEM (2 * NSTG * ASZ)   // 96 KB

template <int EPI, bool CK, bool OUTH>
__global__ __launch_bounds__(256, 2)
void tgemm(const __half* __restrict__ A, const __half* __restrict__ B,
           void* __restrict__ Cv, int M, int N, int K,
           long sA, long sB, long sC, float alpha,
           const float* __restrict__ bias, const __half* __restrict__ resid, long sR)
{
    int bz, m0, NK;
    if (EPI == 5) {
        const int rowTile = (int)gridDim.y - 1 - (int)blockIdx.y;  // longest first
        m0 = rowTile * TILE;
        const int hf = blockIdx.z & 1;
        bz = blockIdx.z >> 1;
        NK = rowTile + 1;                              // iters per half (BK=64)
        const long kBeg = (long)hf * NK * BKk;
        A += (size_t)bz * sA + kBeg;
        B += (size_t)bz * sB + kBeg;
    } else {
        if (EPI == 1 && blockIdx.x > blockIdx.y) return;
        bz = blockIdx.z;
        A += (size_t)bz * sA;  B += (size_t)bz * sB;
        m0 = blockIdx.y * TILE;
        const int Keff = CK ? min(K, (int)(blockIdx.y + 1) * TILE) : K;
        NK = Keff / BKk;
    }
    const int n0 = blockIdx.x * TILE;

    extern __shared__ char smb[];
    const uint32_t smA = smem_u32(smb);
    const uint32_t smB = smA + NSTG * ASZ;

    const int t    = threadIdx.x;
    const int lane = t & 31;
    const int wid  = t >> 5;
    const int wRow = wid >> 2;        // 0..1
    const int wCol = wid & 3;         // 0..3

    const int lrow  = t >> 3;         // 0..31
    const int lchnk = t & 7;          // 0..7

    auto load_stage = [&](int s, int kc) {
        const uint32_t da = smA + s * ASZ;
        const uint32_t db = smB + s * ASZ;
#pragma unroll
        for (int r = 0; r < 4; r++) {
            const int row  = lrow + r * 32;
            const int phys = lchnk ^ (row & 7);
            CPA(da + row * 128 + phys * 16,
                A + (size_t)(m0 + row) * K + kc * BKk + lchnk * 8);
            CPA(db + row * 128 + phys * 16,
                B + (size_t)(n0 + row) * K + kc * BKk + lchnk * 8);
        }
    };

    const int aRowOff = lane & 15;
    const int aChHalf = lane >> 4;
    const int bRowOff = ((lane >> 4) & 1) * 8 + (lane & 7);
    const int bChHalf = (lane >> 3) & 1;

    float acc[4][4][4];
#pragma unroll
    for (int i = 0; i < 4; i++)
#pragma unroll
        for (int j = 0; j < 4; j++)
#pragma unroll
            for (int e = 0; e < 4; e++) acc[i][j][e] = 0.f;

#pragma unroll
    for (int s = 0; s < NSTG - 1; s++) { load_stage(s, s); CPC(); }

    for (int it = 0; it < NK; it++) {
        CPW(1);
        __syncthreads();
        if (it + NSTG - 1 < NK) load_stage((it + NSTG - 1) % NSTG, it + NSTG - 1);
        CPC();

        const int s = it % NSTG;
        const uint32_t aBase = smA + s * ASZ;
        const uint32_t bBase = smB + s * ASZ;

#pragma unroll
        for (int kk = 0; kk < 4; kk++) {
            const int kb = kk * 2;
            uint32_t af[4][4], bf[4][2];
#pragma unroll
            for (int mt = 0; mt < 4; mt++) {
                const int row   = wRow * 64 + mt * 16 + aRowOff;
                const int chunk = kb + aChHalf;
                const uint32_t addr = aBase + row * 128 + ((chunk ^ (row & 7)) << 4);
                LDSM4(af[mt][0], af[mt][1], af[mt][2], af[mt][3], addr);
            }
#pragma unroll
            for (int p = 0; p < 2; p++) {
                const int row   = wCol * 32 + p * 16 + bRowOff;
                const int chunk = kb + bChHalf;
                const uint32_t addr = bBase + row * 128 + ((chunk ^ (row & 7)) << 4);
                LDSM4(bf[2 * p][0], bf[2 * p][1], bf[2 * p + 1][0], bf[2 * p + 1][1], addr);
            }
#pragma unroll
            for (int mt = 0; mt < 4; mt++)
#pragma unroll
                for (int nt = 0; nt < 4; nt++) {
                    float* d = acc[mt][nt];
                    asm volatile(
                        "mma.sync.aligned.m16n8k16.row.col.f32.f16.f16.f32 "
                        "{%0,%1,%2,%3}, {%4,%5,%6,%7}, {%8,%9}, {%0,%1,%2,%3};"
                        : "+f"(d[0]), "+f"(d[1]), "+f"(d[2]), "+f"(d[3])
                        : "r"(af[mt][0]), "r"(af[mt][1]), "r"(af[mt][2]), "r"(af[mt][3]),
                          "r"(bf[nt][0]), "r"(bf[nt][1]));
                }
        }
    }

    // ---- epilogue ----
    float*  Cf = (float*)Cv  + (size_t)bz * sC;
    __half* Ch = (__half*)Cv + (size_t)bz * sC;
    const int g = lane >> 2;
    const int c = lane & 3;
#pragma unroll
    for (int mt = 0; mt < 4; mt++) {
#pragma unroll
        for (int nt = 0; nt < 4; nt++) {
            const int row0 = m0 + wRow * 64 + mt * 16 + g;
            const int col0 = n0 + wCol * 32 + nt * 8 + 2 * c;
            float* d = acc[mt][nt];
#pragma unroll
            for (int half_ = 0; half_ < 2; half_++) {
                const int row = row0 + half_ * 8;
                float v0 = d[half_ * 2 + 0];
                float v1 = d[half_ * 2 + 1];
                if (EPI == 5) {
                    atomicAdd(&Cf[(size_t)row * N + col0],     v0);
                    atomicAdd(&Cf[(size_t)row * N + col0 + 1], v1);
                    continue;
                }
                if (EPI == 1) {
                    v0 = (col0 <= row)     ? v0 * alpha : NEGV;
                    v1 = (col0 + 1 <= row) ? v1 * alpha : NEGV;
                }
                if (EPI == 3) { v0 += bias[col0]; v1 += bias[col0 + 1]; }
                if (EPI == 4) {
                    v0 = v0 / (1.f + __expf(-v0));
                    v1 = v1 / (1.f + __expf(-v1));
                }
                if (OUTH) {
                    __half2 hv = __floats2half2_rn(v0, v1);
                    *(__half2*)&Ch[(size_t)row * N + col0] = hv;
                } else {
                    *(float2*)&Cf[(size_t)row * N + col0] = make_float2(v0, v1);
                }
            }
        }
    }
}

// ---------------------------------------------------------------------------
__global__ void half_copy(const float* __restrict__ in, __half* __restrict__ out) {
    const int i = (blockIdx.x * 256 + threadIdx.x) * 4;
    float4 v = *(const float4*)(in + i);
    *(__half2*)(out + i)     = __floats2half2_rn(v.x, v.y);
    *(__half2*)(out + i + 2) = __floats2half2_rn(v.z, v.w);
}

__global__ void transpose_f2h(const float* __restrict__ in, __half* __restrict__ out,
                              int R, int C) {
    __shared__ __half tile[32][34];
    const int r0 = blockIdx.y * 32, c0 = blockIdx.x * 32;
    const int tx = threadIdx.x, ty = threadIdx.y;
#pragma unroll
    for (int j = 0; j < 4; j++)
        tile[ty + j * 8][tx] = __float2half(in[(size_t)(r0 + ty + j * 8) * C + c0 + tx]);
    __syncthreads();
#pragma unroll
    for (int j = 0; j < 4; j++)
        out[(size_t)(c0 + ty + j * 8) * R + r0 + tx] = tile[tx][ty + j * 8];
}

__global__ void transpose_h(const __half* __restrict__ in, __half* __restrict__ out,
                            int R, int C, long sI, long sO) {
    __shared__ __half tile[32][34];
    const __half* I = in  + (size_t)blockIdx.z * sI;
    __half*       O = out + (size_t)blockIdx.z * sO;
    const int r0 = blockIdx.y * 32, c0 = blockIdx.x * 32;
    const int tx = threadIdx.x, ty = threadIdx.y;
#pragma unroll
    for (int j = 0; j < 4; j++)
        tile[ty + j * 8][tx] = I[(size_t)(r0 + ty + j * 8) * C + c0 + tx];
    __syncthreads();
#pragma unroll
    for (int j = 0; j < 4; j++)
        O[(size_t)(c0 + ty + j * 8) * R + r0 + tx] = tile[tx][ty + j * 8];
}

__global__ void fold_transpose(const float* __restrict__ ok, __half* __restrict__ out) {
    __shared__ __half tile[32][34];
    const int k0 = blockIdx.x * 32, n0 = blockIdx.y * 32;
    const int tx = threadIdx.x, ty = threadIdx.y;
    float acc[4] = {0.f, 0.f, 0.f, 0.f};
    for (int h = 0; h < Hn; h++)
#pragma unroll
        for (int j = 0; j < 4; j++)
            acc[j] += ok[(size_t)h * Dm * Dm + (size_t)(k0 + ty + 8 * j) * Dm + n0 + tx];
#pragma unroll
    for (int j = 0; j < 4; j++) tile[ty + 8 * j][tx] = __float2half(acc[j]);
    __syncthreads();
#pragma unroll
    for (int j = 0; j < 4; j++)
        out[(size_t)(n0 + ty + 8 * j) * Dm + k0 + tx] = tile[tx][ty + 8 * j];
}

// PV epilogue: headh = half(hpv + q)
__global__ void pv_epi(const float* __restrict__ buf, const __half* __restrict__ qh,
                       __half* __restrict__ headh) {
    const size_t i = ((size_t)blockIdx.x * 256 + threadIdx.x) * 4;
    float4 a = *(const float4*)(buf + i);
    const __half2 q01 = *(const __half2*)(qh + i);
    const __half2 q23 = *(const __half2*)(qh + i + 2);
    float2 f01 = __half22float2(q01);
    float2 f23 = __half22float2(q23);
    *(__half2*)(headh + i)     = __floats2half2_rn(a.x + f01.x, a.y + f01.y);
    *(__half2*)(headh + i + 2) = __floats2half2_rn(a.z + f23.x, a.w + f23.y);
}

// ---------------------------------------------------------------------------
// Row softmax over causal prefix: fp32 scores in, fp16 probs out.
// float4 I/O, shuffle + 8-way smem reductions (2 barriers total).
// ---------------------------------------------------------------------------
__global__ void softmax_rows(const float* __restrict__ sc, __half* __restrict__ ph) {
    const int rowg = blockIdx.x;
    const int b = rowg >> 11, r = rowg & 2047;
    const float* p = sc + (size_t)b * Sq * Sq + (size_t)r * Sq;
    __half* po = ph + (size_t)b * Sq * Sq + (size_t)r * Sq;
    const int L  = ((r >> 7) + 1) << 7;
    const int n4 = L >> 2;                    // float4 count: 32..512
    const int t = threadIdx.x, lane = t & 31, w = t >> 5;

    float4 v[2];
    int cnt = 0;
    float mx = -INFINITY;
    for (int j = t; j < n4; j += 256) {
        float4 x = *(const float4*)(p + j * 4);
        v[cnt++] = x;
        mx = fmaxf(fmaxf(mx, fmaxf(x.x, x.y)), fmaxf(x.z, x.w));
    }
#pragma unroll
    for (int o = 16; o > 0; o >>= 1) mx = fmaxf(mx, __shfl_xor_sync(0xFFFFFFFFu, mx, o));
    __shared__ float sm[8], ss[8];
    if (lane == 0) sm[w] = mx;
    __syncthreads();
    float m2 = -INFINITY;
#pragma unroll
    for (int i = 0; i < 8; i++) m2 = fmaxf(m2, sm[i]);

    float sum = 0.f;
    for (int i = 0; i < cnt; i++) {
        v[i].x = __expf(v[i].x - m2); v[i].y = __expf(v[i].y - m2);
        v[i].z = __expf(v[i].z - m2); v[i].w = __expf(v[i].w - m2);
        sum += v[i].x + v[i].y + v[i].z + v[i].w;
    }
#pragma unroll
    for (int o = 16; o > 0; o >>= 1) sum += __shfl_xor_sync(0xFFFFFFFFu, sum, o);
    if (lane == 0) ss[w] = sum;
    __syncthreads();
    float tot = 0.f;
#pragma unroll
    for (int i = 0; i < 8; i++) tot += ss[i];
    const float inv = 1.f / tot;

    cnt = 0;
    for (int j = t; j < n4; j += 256) {
        float4 x = v[cnt++];
        *(__half2*)(po + j * 4)     = __floats2half2_rn(x.x * inv, x.y * inv);
        *(__half2*)(po + j * 4 + 2) = __floats2half2_rn(x.z * inv, x.w * inv);
    }
}

// LayerNorm: fp32 in, fp16 out; shuffle + 8-way smem reduction (1 barrier).
__global__ void layernorm_rows(const float* __restrict__ h, __half* __restrict__ hh) {
    const int row = blockIdx.x;
    const float* p = h + (size_t)row * Dm;
    __half* po = hh + (size_t)row * Dm;
    const int t = threadIdx.x, lane = t & 31, w = t >> 5;
    float4 v = *(const float4*)&p[t * 4];
    float s  = v.x + v.y + v.z + v.w;
    float sq = v.x * v.x + v.y * v.y + v.z * v.z + v.w * v.w;
#pragma unroll
    for (int o = 16; o > 0; o >>= 1) {
        s  += __shfl_xor_sync(0xFFFFFFFFu, s, o);
        sq += __shfl_xor_sync(0xFFFFFFFFu, sq, o);
    }
    __shared__ float rs[8], rq[8];
    if (lane == 0) { rs[w] = s; rq[w] = sq; }
    __syncthreads();
    float S = 0.f, Q = 0.f;
#pragma unroll
    for (int i = 0; i < 8; i++) { S += rs[i]; Q += rq[i]; }
    const float mean = S * (1.f / Dm);
    const float var  = Q * (1.f / Dm) - mean * mean;
    const float inv  = rsqrtf(var + 1e-5f);
    *(__half2*)&po[t * 4]     = __floats2half2_rn((v.x - mean) * inv, (v.y - mean) * inv);
    *(__half2*)&po[t * 4 + 2] = __floats2half2_rn((v.z - mean) * inv, (v.w - mean) * inv);
}

// ---------------------------------------------------------------------------
extern "C" void kernel_launch(void* const* d_in, const int* in_sizes, int n_in,
                              void* d_out, int out_size)
{
    const float* x  = (const float*)d_in[0];
    const float* wi = (const float*)d_in[2];
    const float* ok = (const float*)d_in[3];
    const float* ob = (const float*)d_in[4];
    float* out = (float*)d_out;

    __half *xh, *qh, *qTh, *ph, *headh, *hh, *acth, *weffTh, *wiTh;
    float *sc, *h, *hpv;
    cudaGetSymbolAddress((void**)&xh,     g_xh);
    cudaGetSymbolAddress((void**)&qh,     g_qh);
    cudaGetSymbolAddress((void**)&qTh,    g_qTh);
    cudaGetSymbolAddress((void**)&sc,     g_sc);
    cudaGetSymbolAddress((void**)&ph,     g_ph);
    cudaGetSymbolAddress((void**)&hpv,    g_hpv);
    cudaGetSymbolAddress((void**)&headh,  g_headh);
    cudaGetSymbolAddress((void**)&h,      g_h);
    cudaGetSymbolAddress((void**)&hh,     g_hh);
    cudaGetSymbolAddress((void**)&acth,   g_acth);
    cudaGetSymbolAddress((void**)&weffTh, g_weffTh);
    cudaGetSymbolAddress((void**)&wiTh,   g_wiTh);

    cudaFuncSetAttribute(tgemm<0, false, true>,  cudaFuncAttributeMaxDynamicSharedMemorySize, DSMEM);
    cudaFuncSetAttribute(tgemm<1, false, false>, cudaFuncAttributeMaxDynamicSharedMemorySize, DSMEM);
    cudaFuncSetAttribute(tgemm<5, false, false>, cudaFuncAttributeMaxDynamicSharedMemorySize, DSMEM);
    cudaFuncSetAttribute(tgemm<3, false, false>, cudaFuncAttributeMaxDynamicSharedMemorySize, DSMEM);
    cudaFuncSetAttribute(tgemm<4, false, true>,  cudaFuncAttributeMaxDynamicSharedMemorySize, DSMEM);
    cudaFuncSetAttribute(tgemm<0, false, false>, cudaFuncAttributeMaxDynamicSharedMemorySize, DSMEM);

    const int MS = Bsz * Sq;            // 4096
    const long sQ  = (long)Sq * Dm;
    const long sSS = (long)Sq * Sq;

    // zero PV accumulator (graph-capturable async memset on existing buffer)
    cudaMemsetAsync(hpv, 0, (size_t)Bsz * Sq * Dm * sizeof(float));

    // producers: fp16 operands
    half_copy<<<(Bsz * Sq * Dm) / 1024, 256>>>(x, xh);
    fold_transpose<<<dim3(Dm / 32, Dm / 32), dim3(32, 8)>>>(ok, weffTh);
    transpose_f2h<<<dim3(Dm / 32, Dm / 32), dim3(32, 8)>>>(wi, wiTh, Dm, Dm);

    // q = x @ wi (half out)
    tgemm<0, false, true><<<dim3(Dm / TILE, MS / TILE, 1), 256, DSMEM>>>(
        xh, wiTh, qh, MS, Dm, Dm, 0, 0, 0, 0.f, nullptr, nullptr, 0);

    transpose_h<<<dim3(Dm / 32, Sq / 32, Bsz), dim3(32, 8)>>>(qh, qTh, Sq, Dm, sQ, sQ);

    // scores = (q @ q^T)/32 causal (fp32 out)
    tgemm<1, false, false><<<dim3(Sq / TILE, Sq / TILE, Bsz), 256, DSMEM>>>(
        qh, qh, sc, Sq, Sq, Dm, sQ, sQ, sSS, 1.f / 32.f, nullptr, nullptr, 0);

    softmax_rows<<<Bsz * Sq, 256>>>(sc, ph);

    // PV split-K: hpv += P @ q  (512 balanced CTAs, longest-first)
    tgemm<5, false, false><<<dim3(Dm / TILE, Sq / TILE, Bsz * 2), 256, DSMEM>>>(
        ph, qTh, hpv, Sq, Dm, Sq, sSS, sQ, sQ, 0.f, nullptr, nullptr, 0);

    // head = hpv + q (half out)
    pv_epi<<<(Bsz * Sq * Dm) / 1024, 256>>>(hpv, qh, headh);

    // h = head @ Weff + bias (fp32 out for LN)
    tgemm<3, false, false><<<dim3(Dm / TILE, MS / TILE, 1), 256, DSMEM>>>(
        headh, weffTh, h, MS, Dm, Dm, 0, 0, 0, 0.f, ob, nullptr, 0);

    layernorm_rows<<<Bsz * Sq, 256>>>(h, hh);

    // act = swish(h @ wi) (half out)
    tgemm<4, false, true><<<dim3(Dm / TILE, MS / TILE, 1), 256, DSMEM>>>(
        hh, wiTh, acth, MS, Dm, Dm, 0, 0, 0, 0.f, nullptr, nullptr, 0);

    // out = act @ wi (fp32 final)
    tgemm<0, false, false><<<dim3(Dm / TILE, MS / TILE, 1), 256, DSMEM>>>(
        acth, wiTh, out, MS, Dm, Dm, 0, 0, 0, 0.f, nullptr, nullptr, 0);
}